// round 7
// baseline (speedup 1.0000x reference)
#include <cuda_runtime.h>
#include <cuda_fp16.h>
#include <cstdint>

#define NROW 1024
#define KDIM 2048
#define NF   128
#define SPLITK 8
#define KCHUNK (KDIM / SPLITK)   // 256
#define BK 64

// ---------------------------------------------------------------------------
// Device scratch
// ---------------------------------------------------------------------------
__device__ __half g_fhi16[NF * KDIM];            // feats (fp16, rounded)
__device__ float  g_part[SPLITK * 2048 * NF];    // split-K partials [ks][m][n]
__device__ __half g_shi[2048 * NF];              // relu(scores) hi, [m][k]
__device__ __half g_slo[NROW * NF];              // relu(scores) lo, a-rows only

// ---------------------------------------------------------------------------
// Helpers
// ---------------------------------------------------------------------------
__device__ __forceinline__ uint32_t su32(const void* p) {
    return (uint32_t)__cvta_generic_to_shared(p);
}
__device__ __forceinline__ uint32_t pk(__half a, __half b) {
    __half2 h = __halves2half2(a, b);
    return *reinterpret_cast<uint32_t*>(&h);
}
__device__ __forceinline__ void cp16(uint32_t dst, const void* src) {
    asm volatile("cp.async.ca.shared.global [%0], [%1], 16;" :: "r"(dst), "l"(src));
}

#define CP_COMMIT() asm volatile("cp.async.commit_group;" ::: "memory")
#define CP_WAIT0()  asm volatile("cp.async.wait_group 0;"  ::: "memory")

#define LDSM4(R, addr) \
    asm volatile("ldmatrix.sync.aligned.m8n8.x4.shared.b16 {%0,%1,%2,%3}, [%4];" \
        : "=r"((R)[0]), "=r"((R)[1]), "=r"((R)[2]), "=r"((R)[3]) : "r"(addr))

#define MMA(C, A, b0, b1) \
    asm volatile("mma.sync.aligned.m16n8k16.row.col.f32.f16.f16.f32 " \
        "{%0,%1,%2,%3}, {%4,%5,%6,%7}, {%8,%9}, {%0,%1,%2,%3};" \
        : "+f"((C)[0]), "+f"((C)[1]), "+f"((C)[2]), "+f"((C)[3]) \
        : "r"((A)[0]), "r"((A)[1]), "r"((A)[2]), "r"((A)[3]), "r"(b0), "r"(b1))

// swizzled byte offset, 128B rows (64 halves)
__device__ __forceinline__ uint32_t swz1(int row, int kh) {
    return (uint32_t)(row * 128 + ((((kh >> 3) ^ (row & 7)) << 4)));
}
// swizzled byte offset, 256B rows (128 halves)
__device__ __forceinline__ uint32_t swz2(int row, int kh) {
    int c = kh >> 3;
    return (uint32_t)(row * 256 + ((((c & 8) | ((c ^ (row & 7)) & 7)) << 4)));
}

// fp32 -> fp16 hi/lo split of a float4 into packed pairs
__device__ __forceinline__ void split4(float4 v, uint2& hw, uint2& lw) {
    __half h0 = __float2half_rn(v.x), h1 = __float2half_rn(v.y);
    __half h2 = __float2half_rn(v.z), h3 = __float2half_rn(v.w);
    __half l0 = __float2half_rn(v.x - __half2float(h0));
    __half l1 = __float2half_rn(v.y - __half2float(h1));
    __half l2 = __float2half_rn(v.z - __half2float(h2));
    __half l3 = __float2half_rn(v.w - __half2float(h3));
    hw.x = pk(h0, h1); hw.y = pk(h2, h3);
    lw.x = pk(l0, l1); lw.y = pk(l2, l3);
}
__device__ __forceinline__ uint2 round4(float4 v) {
    uint2 hw;
    hw.x = pk(__float2half_rn(v.x), __float2half_rn(v.y));
    hw.y = pk(__float2half_rn(v.z), __float2half_rn(v.w));
    return hw;
}

// ---------------------------------------------------------------------------
// Prep: feats fp32 -> fp16 (rounded, row-major [NF][KDIM])
// ---------------------------------------------------------------------------
__global__ void prep_feats(const float* __restrict__ f) {
    int g = blockIdx.x * blockDim.x + threadIdx.x;   // 32768 threads
    size_t base = (size_t)g * 8;                     // 256K elements
    *(uint2*)&g_fhi16[base]     = round4(*(const float4*)&f[base]);
    *(uint2*)&g_fhi16[base + 4] = round4(*(const float4*)&f[base + 4]);
}

// ---------------------------------------------------------------------------
// Stage 1: g_part[ks][m 128-tile][0..127] = X[m, kchunk] . feats^T
// 2-term split: Xhi.F + Xlo.F (F rounded fp16).
// grid (16 m, 8 ks), 512 threads (16 warps, warp tile 32m x 32n).
// smem per buffer (49152B): XHI +0, XLO +16384, FHI +32768; two buffers.
// ---------------------------------------------------------------------------
__global__ __launch_bounds__(512, 1) void stage1(const float* __restrict__ A_,
                                                 const float* __restrict__ B_) {
    extern __shared__ char smem[];
    const uint32_t sb = su32(smem);
    const int t = threadIdx.x, lane = t & 31, wid = t >> 5;
    const int m0 = blockIdx.x * 128;
    const int ks = blockIdx.y;
    const float* X = (m0 < NROW) ? A_ : B_;
    const int mb = (m0 < NROW) ? m0 : m0 - NROW;
    const int kbase = ks * KCHUNK;

    const int wy = wid & 3, wx = wid >> 2;
    const int m0w = wy * 32, n0w = wx * 32;
    const int aRow = lane & 15, aK = (lane >> 4) << 3;
    const int bN = ((lane >> 4) << 3) + (lane & 7), bK = ((lane >> 3) & 1) << 3;

    float acc[2][4][4];
    #pragma unroll
    for (int i = 0; i < 2; i++)
        #pragma unroll
        for (int j = 0; j < 4; j++)
            #pragma unroll
            for (int q = 0; q < 4; q++) acc[i][j][q] = 0.f;

    float xr[2][8];

    // ---- slab 0 prologue ----
    {
        const int kk = kbase;
        #pragma unroll
        for (int i = 0; i < 2; i++) {
            int chunk = t + i * 512; int row = chunk >> 3, c = chunk & 7;
            uint32_t off = (uint32_t)(row * 128 + (((c ^ (row & 7)) << 4)));
            cp16(sb + 32768 + off, &g_fhi16[row * KDIM + kk + c * 8]);
            const float* src = &X[(size_t)(mb + row) * KDIM + kk + c * 8];
            *(float4*)&xr[i][0] = *(const float4*)src;
            *(float4*)&xr[i][4] = *(const float4*)(src + 4);
        }
        CP_COMMIT();
        #pragma unroll
        for (int i = 0; i < 2; i++) {
            int chunk = t + i * 512; int row = chunk >> 3, c = chunk & 7;
            uint32_t off = (uint32_t)(row * 128 + (((c ^ (row & 7)) << 4)));
            uint2 hw0, lw0, hw1, lw1;
            split4(*(float4*)&xr[i][0], hw0, lw0);
            split4(*(float4*)&xr[i][4], hw1, lw1);
            *(uint4*)(smem + off)         = make_uint4(hw0.x, hw0.y, hw1.x, hw1.y);
            *(uint4*)(smem + 16384 + off) = make_uint4(lw0.x, lw0.y, lw1.x, lw1.y);
        }
        CP_WAIT0();
        __syncthreads();
    }

    // ---- main loop over 4 slabs ----
    #pragma unroll 1
    for (int s = 0; s < 4; s++) {
        const int p = s & 1, np = p ^ 1;
        if (s < 3) {
            const int kk = kbase + (s + 1) * BK;
            uint32_t nb = sb + np * 49152;
            #pragma unroll
            for (int i = 0; i < 2; i++) {
                int chunk = t + i * 512; int row = chunk >> 3, c = chunk & 7;
                uint32_t off = (uint32_t)(row * 128 + (((c ^ (row & 7)) << 4)));
                cp16(nb + 32768 + off, &g_fhi16[row * KDIM + kk + c * 8]);
                const float* src = &X[(size_t)(mb + row) * KDIM + kk + c * 8];
                *(float4*)&xr[i][0] = *(const float4*)src;
                *(float4*)&xr[i][4] = *(const float4*)(src + 4);
            }
            CP_COMMIT();
        }

        const uint32_t base = sb + p * 49152;
        #pragma unroll
        for (int k16 = 0; k16 < 4; k16++) {
            const int kh = k16 * 16;
            uint32_t ah[2][4], al[2][4], bh[2][4];
            #pragma unroll
            for (int mt = 0; mt < 2; mt++) {
                uint32_t ra = base + swz1(m0w + mt * 16 + aRow, kh + aK);
                LDSM4(ah[mt], ra);
                LDSM4(al[mt], ra + 16384);
            }
            #pragma unroll
            for (int g = 0; g < 2; g++) {
                uint32_t rb = base + 32768 + swz1(n0w + g * 16 + bN, kh + bK);
                LDSM4(bh[g], rb);
            }
            #pragma unroll
            for (int mt = 0; mt < 2; mt++)
                #pragma unroll
                for (int nt = 0; nt < 4; nt++) {
                    uint32_t h0 = bh[nt >> 1][(nt & 1) * 2], h1 = bh[nt >> 1][(nt & 1) * 2 + 1];
                    MMA(acc[mt][nt], ah[mt], h0, h1);
                    MMA(acc[mt][nt], al[mt], h0, h1);
                }
        }

        if (s < 3) {
            const uint32_t nboff = (uint32_t)(np * 49152);
            #pragma unroll
            for (int i = 0; i < 2; i++) {
                int chunk = t + i * 512; int row = chunk >> 3, c = chunk & 7;
                uint32_t off = nboff + (uint32_t)(row * 128 + (((c ^ (row & 7)) << 4)));
                uint2 hw0, lw0, hw1, lw1;
                split4(*(float4*)&xr[i][0], hw0, lw0);
                split4(*(float4*)&xr[i][4], hw1, lw1);
                *(uint4*)(smem + off)         = make_uint4(hw0.x, hw0.y, hw1.x, hw1.y);
                *(uint4*)(smem + 16384 + off) = make_uint4(lw0.x, lw0.y, lw1.x, lw1.y);
            }
            CP_WAIT0();
        }
        __syncthreads();
    }

    // ---- epilogue: fp32 partials ----
    float* dst = g_part + (size_t)ks * (2048 * NF);
    #pragma unroll
    for (int mt = 0; mt < 2; mt++)
        #pragma unroll
        for (int nt = 0; nt < 4; nt++) {
            int r = m0 + m0w + mt * 16 + (lane >> 2);
            int cc = n0w + nt * 8 + (lane & 3) * 2;
            *(float2*)&dst[(size_t)r * NF + cc] =
                make_float2(acc[mt][nt][0], acc[mt][nt][1]);
            *(float2*)&dst[(size_t)(r + 8) * NF + cc] =
                make_float2(acc[mt][nt][2], acc[mt][nt][3]);
        }
}

// ---------------------------------------------------------------------------
// Reduce: sum split-K partials, relu; hi for all rows, lo for a-rows only
// ---------------------------------------------------------------------------
__global__ void reduce_relu() {
    int g = blockIdx.x * blockDim.x + threadIdx.x;   // 65536 threads
    size_t o = (size_t)g * 4;
    float4 s = make_float4(0.f, 0.f, 0.f, 0.f);
    #pragma unroll
    for (int p = 0; p < SPLITK; p++) {
        float4 v = *(const float4*)&g_part[(size_t)p * (2048 * NF) + o];
        s.x += v.x; s.y += v.y; s.z += v.z; s.w += v.w;
    }
    s.x = fmaxf(s.x, 0.f); s.y = fmaxf(s.y, 0.f);
    s.z = fmaxf(s.z, 0.f); s.w = fmaxf(s.w, 0.f);
    uint2 hw, lw;
    split4(s, hw, lw);
    *(uint2*)&g_shi[o] = hw;
    if ((o >> 7) < NROW) *(uint2*)&g_slo[o] = lw;    // a-rows only
}

// ---------------------------------------------------------------------------
// Stage 2: out[i][j] = sum_k (shi+slo)[i][k] * shi[1024+j][k]  (2-term)
// grid (16 j, 16 i): CTA 64i x 64j, 256 threads (8 warps, warp tile 32i x 16j).
// smem 48KB: AHI +0, ALO +16384, BHI +32768.
// 4-deep cp.async pipeline over K=32 chunks; compute chunk c after
// wait_group(3-c).
// ---------------------------------------------------------------------------
__global__ __launch_bounds__(256, 2) void stage2(float* __restrict__ out) {
    extern __shared__ char smem[];
    const uint32_t sb = su32(smem);
    const int t = threadIdx.x, lane = t & 31, wid = t >> 5;
    const int it = blockIdx.y * 64, jt = blockIdx.x * 64;
    const int wy = wid & 1, wx = wid >> 1;
    const int m0w = wy * 32, n0w = wx * 16;

    // issue all 4 K-chunk groups up front (each: 64B of K per row)
    {
        const int row = t >> 2;                      // 0..63
        const size_t ra = (size_t)(it + row) * NF;
        const size_t rb = (size_t)(1024 + jt + row) * NF;
        #pragma unroll
        for (int cc = 0; cc < 4; cc++) {
            int u = (t & 3) + cc * 4;                // 8-half unit 0..15
            uint32_t off = swz2(row, u * 8);
            cp16(sb + off,         &g_shi[ra + u * 8]);
            cp16(sb + 16384 + off, &g_slo[ra + u * 8]);
            cp16(sb + 32768 + off, &g_shi[rb + u * 8]);
            CP_COMMIT();
        }
    }

    const int aRow = lane & 15, aK = (lane >> 4) << 3;
    const int bN = ((lane >> 4) << 3) + (lane & 7), bK = ((lane >> 3) & 1) << 3;

    float acc[2][2][4];
    #pragma unroll
    for (int i = 0; i < 2; i++)
        #pragma unroll
        for (int j = 0; j < 2; j++)
            #pragma unroll
            for (int q = 0; q < 4; q++) acc[i][j][q] = 0.f;

    #pragma unroll
    for (int cc = 0; cc < 4; cc++) {
        if (cc == 0)      asm volatile("cp.async.wait_group 3;" ::: "memory");
        else if (cc == 1) asm volatile("cp.async.wait_group 2;" ::: "memory");
        else if (cc == 2) asm volatile("cp.async.wait_group 1;" ::: "memory");
        else              asm volatile("cp.async.wait_group 0;" ::: "memory");
        __syncthreads();

        #pragma unroll
        for (int k16 = 0; k16 < 2; k16++) {
            const int kh = cc * 32 + k16 * 16;
            uint32_t ah[2][4], al[2][4], bh[4];
            #pragma unroll
            for (int mt = 0; mt < 2; mt++) {
                uint32_t ra = sb + swz2(m0w + mt * 16 + aRow, kh + aK);
                LDSM4(ah[mt], ra);
                LDSM4(al[mt], ra + 16384);
            }
            {
                uint32_t rb = sb + 32768 + swz2(n0w + bN, kh + bK);
                LDSM4(bh, rb);
            }
            #pragma unroll
            for (int mt = 0; mt < 2; mt++)
                #pragma unroll
                for (int nt = 0; nt < 2; nt++) {
                    uint32_t h0 = bh[nt * 2], h1 = bh[nt * 2 + 1];
                    MMA(acc[mt][nt], ah[mt], h0, h1);
                    MMA(acc[mt][nt], al[mt], h0, h1);
                }
        }
    }

    #pragma unroll
    for (int mt = 0; mt < 2; mt++)
        #pragma unroll
        for (int nt = 0; nt < 2; nt++) {
            int r = it + m0w + mt * 16 + (lane >> 2);
            int cc = jt + n0w + nt * 8 + (lane & 3) * 2;
            *(float2*)&out[(size_t)r * NROW + cc] =
                make_float2(acc[mt][nt][0], acc[mt][nt][1]);
            *(float2*)&out[(size_t)(r + 8) * NROW + cc] =
                make_float2(acc[mt][nt][2], acc[mt][nt][3]);
        }
}

// ---------------------------------------------------------------------------
extern "C" void kernel_launch(void* const* d_in, const int* in_sizes, int n_in,
                              void* d_out, int out_size) {
    (void)in_sizes; (void)n_in; (void)out_size;
    const float* a = (const float*)d_in[0];
    const float* b = (const float*)d_in[1];
    const float* f = (const float*)d_in[2];
    float* out = (float*)d_out;

    cudaFuncSetAttribute(stage1, cudaFuncAttributeMaxDynamicSharedMemorySize, 98304);
    cudaFuncSetAttribute(stage2, cudaFuncAttributeMaxDynamicSharedMemorySize, 49152);

    prep_feats<<<128, 256>>>(f);
    stage1<<<dim3(16, SPLITK), 512, 98304>>>(a, b);
    reduce_relu<<<256, 256>>>();
    stage2<<<dim3(16, 16), 256, 49152>>>(out);
}

// round 8
// speedup vs baseline: 1.1926x; 1.1926x over previous
#include <cuda_runtime.h>
#include <cuda_fp16.h>
#include <cstdint>

#define NROW 1024
#define KDIM 2048
#define NF   128
#define SPLITK 8
#define KCHUNK (KDIM / SPLITK)   // 256
#define BK 64

// ---------------------------------------------------------------------------
// Device scratch
// ---------------------------------------------------------------------------
__device__ __half g_fhi16[NF * KDIM];            // feats (fp16, rounded)
__device__ float  g_part[SPLITK * 2048 * NF];    // split-K partials [ks][m][n]
__device__ __half g_shi[2048 * NF];              // relu(scores) fp16, [m][k]

// ---------------------------------------------------------------------------
// Helpers
// ---------------------------------------------------------------------------
__device__ __forceinline__ uint32_t su32(const void* p) {
    return (uint32_t)__cvta_generic_to_shared(p);
}
__device__ __forceinline__ uint32_t pk(__half a, __half b) {
    __half2 h = __halves2half2(a, b);
    return *reinterpret_cast<uint32_t*>(&h);
}
__device__ __forceinline__ void cp16(uint32_t dst, const void* src) {
    asm volatile("cp.async.ca.shared.global [%0], [%1], 16;" :: "r"(dst), "l"(src));
}

#define CP_COMMIT() asm volatile("cp.async.commit_group;" ::: "memory")
#define CP_WAIT0()  asm volatile("cp.async.wait_group 0;"  ::: "memory")
#define CP_WAIT1()  asm volatile("cp.async.wait_group 1;"  ::: "memory")

#define LDSM4(R, addr) \
    asm volatile("ldmatrix.sync.aligned.m8n8.x4.shared.b16 {%0,%1,%2,%3}, [%4];" \
        : "=r"((R)[0]), "=r"((R)[1]), "=r"((R)[2]), "=r"((R)[3]) : "r"(addr))

#define MMA(C, A, b0, b1) \
    asm volatile("mma.sync.aligned.m16n8k16.row.col.f32.f16.f16.f32 " \
        "{%0,%1,%2,%3}, {%4,%5,%6,%7}, {%8,%9}, {%0,%1,%2,%3};" \
        : "+f"((C)[0]), "+f"((C)[1]), "+f"((C)[2]), "+f"((C)[3]) \
        : "r"((A)[0]), "r"((A)[1]), "r"((A)[2]), "r"((A)[3]), "r"(b0), "r"(b1))

// swizzled byte offset, 128B rows (64 halves)
__device__ __forceinline__ uint32_t swz1(int row, int kh) {
    return (uint32_t)(row * 128 + ((((kh >> 3) ^ (row & 7)) << 4)));
}
// swizzled byte offset, 256B rows (128 halves)
__device__ __forceinline__ uint32_t swz2(int row, int kh) {
    int c = kh >> 3;
    return (uint32_t)(row * 256 + ((((c & 8) | ((c ^ (row & 7)) & 7)) << 4)));
}

__device__ __forceinline__ uint2 round4(float4 v) {
    uint2 hw;
    hw.x = pk(__float2half_rn(v.x), __float2half_rn(v.y));
    hw.y = pk(__float2half_rn(v.z), __float2half_rn(v.w));
    return hw;
}

// ---------------------------------------------------------------------------
// Prep: feats fp32 -> fp16 (rounded, row-major [NF][KDIM])
// ---------------------------------------------------------------------------
__global__ void prep_feats(const float* __restrict__ f) {
    int g = blockIdx.x * blockDim.x + threadIdx.x;   // 32768 threads
    size_t base = (size_t)g * 8;                     // 256K elements
    *(uint2*)&g_fhi16[base]     = round4(*(const float4*)&f[base]);
    *(uint2*)&g_fhi16[base + 4] = round4(*(const float4*)&f[base + 4]);
}

// ---------------------------------------------------------------------------
// Stage 1: g_part[ks][m 128-tile][0..127] = X[m, kchunk] . feats^T
// Single-term fp16 (both operands rounded).
// grid (16 m, 8 ks), 512 threads (16 warps, warp tile 32m x 32n).
// smem per buffer (32768B): XHI +0, FHI +16384; two buffers = 64KB.
// ---------------------------------------------------------------------------
__global__ __launch_bounds__(512, 1) void stage1(const float* __restrict__ A_,
                                                 const float* __restrict__ B_) {
    extern __shared__ char smem[];
    const uint32_t sb = su32(smem);
    const int t = threadIdx.x, lane = t & 31, wid = t >> 5;
    const int m0 = blockIdx.x * 128;
    const int ks = blockIdx.y;
    const float* X = (m0 < NROW) ? A_ : B_;
    const int mb = (m0 < NROW) ? m0 : m0 - NROW;
    const int kbase = ks * KCHUNK;

    const int wy = wid & 3, wx = wid >> 2;
    const int m0w = wy * 32, n0w = wx * 32;
    const int aRow = lane & 15, aK = (lane >> 4) << 3;
    const int bN = ((lane >> 4) << 3) + (lane & 7), bK = ((lane >> 3) & 1) << 3;

    float acc[2][4][4];
    #pragma unroll
    for (int i = 0; i < 2; i++)
        #pragma unroll
        for (int j = 0; j < 4; j++)
            #pragma unroll
            for (int q = 0; q < 4; q++) acc[i][j][q] = 0.f;

    float xr[2][8];

    // ---- slab 0 prologue ----
    {
        const int kk = kbase;
        #pragma unroll
        for (int i = 0; i < 2; i++) {
            int chunk = t + i * 512; int row = chunk >> 3, c = chunk & 7;
            uint32_t off = (uint32_t)(row * 128 + (((c ^ (row & 7)) << 4)));
            cp16(sb + 16384 + off, &g_fhi16[row * KDIM + kk + c * 8]);
            const float* src = &X[(size_t)(mb + row) * KDIM + kk + c * 8];
            *(float4*)&xr[i][0] = *(const float4*)src;
            *(float4*)&xr[i][4] = *(const float4*)(src + 4);
        }
        CP_COMMIT();
        #pragma unroll
        for (int i = 0; i < 2; i++) {
            int chunk = t + i * 512; int row = chunk >> 3, c = chunk & 7;
            uint32_t off = (uint32_t)(row * 128 + (((c ^ (row & 7)) << 4)));
            uint2 h0 = round4(*(float4*)&xr[i][0]);
            uint2 h1 = round4(*(float4*)&xr[i][4]);
            *(uint4*)(smem + off) = make_uint4(h0.x, h0.y, h1.x, h1.y);
        }
        CP_WAIT0();
        __syncthreads();
    }

    // ---- main loop over 4 slabs ----
    #pragma unroll 1
    for (int s = 0; s < 4; s++) {
        const int p = s & 1, np = p ^ 1;
        if (s < 3) {
            const int kk = kbase + (s + 1) * BK;
            uint32_t nb = sb + np * 32768;
            #pragma unroll
            for (int i = 0; i < 2; i++) {
                int chunk = t + i * 512; int row = chunk >> 3, c = chunk & 7;
                uint32_t off = (uint32_t)(row * 128 + (((c ^ (row & 7)) << 4)));
                cp16(nb + 16384 + off, &g_fhi16[row * KDIM + kk + c * 8]);
                const float* src = &X[(size_t)(mb + row) * KDIM + kk + c * 8];
                *(float4*)&xr[i][0] = *(const float4*)src;
                *(float4*)&xr[i][4] = *(const float4*)(src + 4);
            }
            CP_COMMIT();
        }

        const uint32_t base = sb + p * 32768;
        #pragma unroll
        for (int k16 = 0; k16 < 4; k16++) {
            const int kh = k16 * 16;
            uint32_t ah[2][4], bh[2][4];
            #pragma unroll
            for (int mt = 0; mt < 2; mt++) {
                uint32_t ra = base + swz1(m0w + mt * 16 + aRow, kh + aK);
                LDSM4(ah[mt], ra);
            }
            #pragma unroll
            for (int g = 0; g < 2; g++) {
                uint32_t rb = base + 16384 + swz1(n0w + g * 16 + bN, kh + bK);
                LDSM4(bh[g], rb);
            }
            #pragma unroll
            for (int mt = 0; mt < 2; mt++)
                #pragma unroll
                for (int nt = 0; nt < 4; nt++) {
                    uint32_t h0 = bh[nt >> 1][(nt & 1) * 2], h1 = bh[nt >> 1][(nt & 1) * 2 + 1];
                    MMA(acc[mt][nt], ah[mt], h0, h1);
                }
        }

        if (s < 3) {
            const uint32_t nboff = (uint32_t)(np * 32768);
            #pragma unroll
            for (int i = 0; i < 2; i++) {
                int chunk = t + i * 512; int row = chunk >> 3, c = chunk & 7;
                uint32_t off = nboff + (uint32_t)(row * 128 + (((c ^ (row & 7)) << 4)));
                uint2 h0 = round4(*(float4*)&xr[i][0]);
                uint2 h1 = round4(*(float4*)&xr[i][4]);
                *(uint4*)(smem + off) = make_uint4(h0.x, h0.y, h1.x, h1.y);
            }
            CP_WAIT0();
        }
        __syncthreads();
    }

    // ---- epilogue: fp32 partials ----
    float* dst = g_part + (size_t)ks * (2048 * NF);
    #pragma unroll
    for (int mt = 0; mt < 2; mt++)
        #pragma unroll
        for (int nt = 0; nt < 4; nt++) {
            int r = m0 + m0w + mt * 16 + (lane >> 2);
            int cc = n0w + nt * 8 + (lane & 3) * 2;
            *(float2*)&dst[(size_t)r * NF + cc] =
                make_float2(acc[mt][nt][0], acc[mt][nt][1]);
            *(float2*)&dst[(size_t)(r + 8) * NF + cc] =
                make_float2(acc[mt][nt][2], acc[mt][nt][3]);
        }
}

// ---------------------------------------------------------------------------
// Reduce: sum split-K partials, relu, round to fp16
// ---------------------------------------------------------------------------
__global__ void reduce_relu() {
    int g = blockIdx.x * blockDim.x + threadIdx.x;   // 65536 threads
    size_t o = (size_t)g * 4;
    float4 s = make_float4(0.f, 0.f, 0.f, 0.f);
    #pragma unroll
    for (int p = 0; p < SPLITK; p++) {
        float4 v = *(const float4*)&g_part[(size_t)p * (2048 * NF) + o];
        s.x += v.x; s.y += v.y; s.z += v.z; s.w += v.w;
    }
    s.x = fmaxf(s.x, 0.f); s.y = fmaxf(s.y, 0.f);
    s.z = fmaxf(s.z, 0.f); s.w = fmaxf(s.w, 0.f);
    *(uint2*)&g_shi[o] = round4(s);
}

// ---------------------------------------------------------------------------
// Stage 2: out[i][j] = sum_k shi[i][k] * shi[1024+j][k]  (single term)
// grid (16 j, 8 i): CTA 128i x 64j, 512 threads (warp tile 32i x 16j).
// smem: AHI +0 (32KB), BHI +32768 (16KB) = 48KB, cp.async 2 K-half groups.
// ---------------------------------------------------------------------------
__global__ __launch_bounds__(512, 1) void stage2(float* __restrict__ out) {
    extern __shared__ char smem[];
    const uint32_t sb = su32(smem);
    const int t = threadIdx.x, lane = t & 31, wid = t >> 5;
    const int it = blockIdx.y * 128, jt = blockIdx.x * 64;
    const int wy = wid & 3, wx = wid >> 2;
    const int m0w = wy * 32, n0w = wx * 16;

    // two K-half commit groups: group cc covers kh [cc*64, cc*64+64)
    #pragma unroll
    for (int cc = 0; cc < 2; cc++) {
        #pragma unroll
        for (int i = 0; i < 2; i++) {
            int idx = t + i * 512;                 // 0..1023
            int row = idx >> 3, c = (idx & 7) + cc * 8;
            uint32_t off = swz2(row, c * 8);
            cp16(sb + off, &g_shi[(size_t)(it + row) * NF + c * 8]);
        }
        {
            int row = t >> 3, c = (t & 7) + cc * 8;   // 512 -> 64 rows
            uint32_t off = swz2(row, c * 8);
            cp16(sb + 32768 + off, &g_shi[(size_t)(1024 + jt + row) * NF + c * 8]);
        }
        CP_COMMIT();
    }

    const int aRow = lane & 15, aK = (lane >> 4) << 3;
    const int bN = ((lane >> 4) << 3) + (lane & 7), bK = ((lane >> 3) & 1) << 3;

    float acc[2][2][4];
    #pragma unroll
    for (int i = 0; i < 2; i++)
        #pragma unroll
        for (int j = 0; j < 2; j++)
            #pragma unroll
            for (int q = 0; q < 4; q++) acc[i][j][q] = 0.f;

    CP_WAIT1();
    __syncthreads();

    #pragma unroll
    for (int half = 0; half < 2; half++) {
        #pragma unroll
        for (int k16 = 0; k16 < 4; k16++) {
            const int kh = half * 64 + k16 * 16;
            uint32_t ah[2][4], bh[4];
            #pragma unroll
            for (int mt = 0; mt < 2; mt++) {
                uint32_t ra = sb + swz2(m0w + mt * 16 + aRow, kh + aK);
                LDSM4(ah[mt], ra);
            }
            {
                uint32_t rb = sb + 32768 + swz2(n0w + bN, kh + bK);
                LDSM4(bh, rb);
            }
            #pragma unroll
            for (int mt = 0; mt < 2; mt++)
                #pragma unroll
                for (int nt = 0; nt < 2; nt++) {
                    uint32_t h0 = bh[nt * 2], h1 = bh[nt * 2 + 1];
                    MMA(acc[mt][nt], ah[mt], h0, h1);
                }
        }
        if (half == 0) {
            CP_WAIT0();
            __syncthreads();
        }
    }

    #pragma unroll
    for (int mt = 0; mt < 2; mt++)
        #pragma unroll
        for (int nt = 0; nt < 2; nt++) {
            int r = it + m0w + mt * 16 + (lane >> 2);
            int cc = jt + n0w + nt * 8 + (lane & 3) * 2;
            *(float2*)&out[(size_t)r * NROW + cc] =
                make_float2(acc[mt][nt][0], acc[mt][nt][1]);
            *(float2*)&out[(size_t)(r + 8) * NROW + cc] =
                make_float2(acc[mt][nt][2], acc[mt][nt][3]);
        }
}

// ---------------------------------------------------------------------------
extern "C" void kernel_launch(void* const* d_in, const int* in_sizes, int n_in,
                              void* d_out, int out_size) {
    (void)in_sizes; (void)n_in; (void)out_size;
    const float* a = (const float*)d_in[0];
    const float* b = (const float*)d_in[1];
    const float* f = (const float*)d_in[2];
    float* out = (float*)d_out;

    cudaFuncSetAttribute(stage1, cudaFuncAttributeMaxDynamicSharedMemorySize, 65536);
    cudaFuncSetAttribute(stage2, cudaFuncAttributeMaxDynamicSharedMemorySize, 49152);

    prep_feats<<<128, 256>>>(f);
    stage1<<<dim3(16, SPLITK), 512, 65536>>>(a, b);
    reduce_relu<<<256, 256>>>();
    stage2<<<dim3(16, 8), 512, 49152>>>(out);
}